// round 1
// baseline (speedup 1.0000x reference)
#include <cuda_runtime.h>

#define Nn   4096
#define INF_ 256
#define OUTF 64
#define KH   4
#define SEG  16
#define MNEG -1e30f

// ---- scratch (no allocations allowed) ----
__device__ float g_Wh[Nn * OUTF];          // 1M floats
__device__ float g_Wh1[Nn];
__device__ float g_Wh2[Nn];
__device__ float g_pm[SEG * KH * Nn];      // partial max per segment
__device__ float g_ps[SEG * KH * Nn];      // partial sum per segment
__device__ float g_L[KH * Nn];             // m + log(s) per column
__device__ unsigned char g_flag[KH * Nn];  // all-masked column flag
__device__ int g_patho;

// ============================================================
// K1: Wh = h @ W  [N,64];  Wh1 = Wh@a[:64];  Wh2 = Wh@a[64:]
// 4 rows per block, 256 threads (thread = (row, f)).
// ============================================================
__global__ void __launch_bounds__(256) k1_wh(const float* __restrict__ h,
                                             const float* __restrict__ W,
                                             const float* __restrict__ a) {
    __shared__ float sh[4][INF_];
    __shared__ float s1[4], s2[4];
    int t = threadIdx.x;
    int row0 = blockIdx.x * 4;

    for (int q = t; q < 4 * INF_; q += 256)
        sh[q >> 8][q & 255] = h[(size_t)row0 * INF_ + q];
    if (t < 4) { s1[t] = 0.f; s2[t] = 0.f; }
    if (blockIdx.x == 0 && t == 0) g_patho = 0;   // reset every launch
    __syncthreads();

    int r = t >> 6, f = t & 63;
    float acc = 0.f;
#pragma unroll 8
    for (int c = 0; c < INF_; ++c)
        acc += sh[r][c] * W[c * OUTF + f];
    g_Wh[(size_t)(row0 + r) * OUTF + f] = acc;

    float p1 = acc * a[f];
    float p2 = acc * a[OUTF + f];
#pragma unroll
    for (int o = 16; o; o >>= 1) {
        p1 += __shfl_down_sync(0xffffffffu, p1, o);
        p2 += __shfl_down_sync(0xffffffffu, p2, o);
    }
    if ((t & 31) == 0) { atomicAdd(&s1[r], p1); atomicAdd(&s2[r], p2); }
    __syncthreads();
    if (t < 4) { g_Wh1[row0 + t] = s1[t]; g_Wh2[row0 + t] = s2[t]; }
}

// ============================================================
// K2: online softmax stats over axis i (columns j), segmented.
// block = (k, j-tile of 256, i-segment); thread = one column j.
// Masked entries (edge==0 -> e=-9e15) skipped; exp underflows to 0
// exactly in the reference too.
// ============================================================
__global__ void __launch_bounds__(256) k2_stats(const float* __restrict__ edge) {
    int b = blockIdx.x;
    int seg = b & (SEG - 1); b >>= 4;
    int jt = b & 15;
    int k  = b >> 4;
    int j = jt * 256 + threadIdx.x;

    float w2 = g_Wh2[j];
    const float* base = edge + (size_t)k * Nn * Nn + j;
    float m = MNEG, s = 0.f;
    int i0 = seg * (Nn / SEG);
#pragma unroll 4
    for (int i = i0; i < i0 + Nn / SEG; ++i) {
        float x = __ldg(base + (size_t)i * Nn);
        if (x > 0.f) {
            float tt = g_Wh1[i] + w2;
            float e = (tt >= 0.f ? tt : 0.2f * tt) * x;   // leaky_relu * edge
            if (e > m) { s = s * __expf(m - e) + 1.f; m = e; }
            else       { s += __expf(e - m); }
        }
    }
    int col = k * Nn + j;
    g_pm[seg * (KH * Nn) + col] = m;
    g_ps[seg * (KH * Nn) + col] = s;
}

// ============================================================
// K2b: merge segments -> L = m + log(s). All-masked column ->
// att = 1/N uniformly (matches reference: max of -9e15 terms).
// ============================================================
__global__ void __launch_bounds__(256) k2_merge() {
    int col = blockIdx.x * 256 + threadIdx.x;
    float m = MNEG, s = 0.f;
#pragma unroll
    for (int g = 0; g < SEG; ++g) {
        float pm = g_pm[g * (KH * Nn) + col];
        float ps = g_ps[g * (KH * Nn) + col];
        if (pm > m) { s = s * __expf(m - pm) + ps; m = pm; }
        else        { s += ps * __expf(pm - m); }
    }
    if (m <= -0.9e30f) {                 // column entirely masked
        g_L[col] = logf((float)Nn);      // att = exp(-L) = 1/N
        g_flag[col] = 1;
        atomicAdd(&g_patho, 1);
    } else {
        g_L[col] = m + logf(s);
        g_flag[col] = 0;
    }
}

// ============================================================
// K3: per (k, row i): att[k,i,:] = exp(e - L[k,:]) (0 if masked);
// write att; sparse-compact nonzeros; hp[i,f] += att_j * Wh[j,f];
// elu epilogue -> out[i, k*64+f].
// Deterministic compaction via per-warp count + prefix scan.
// ============================================================
__global__ void __launch_bounds__(256) k3_attmm(const float* __restrict__ edge,
                                                float* __restrict__ att_out,
                                                float* __restrict__ out,
                                                int write_att) {
    __shared__ float s_a[256];
    __shared__ int   s_jj[256];
    __shared__ int   s_wcnt[8];
    __shared__ float4 s_red[256];

    int t = threadIdx.x;
    int i = blockIdx.x & (Nn - 1);
    int k = blockIdx.x >> 12;

    float w1 = g_Wh1[i];
    const float* erow = edge + (size_t)(k * Nn + i) * Nn;
    float* arow = att_out + (size_t)(k * Nn + i) * Nn;

    int f4 = t & 15, slot = t >> 4;
    int lane = t & 31, w = t >> 5;
    float4 acc = make_float4(0.f, 0.f, 0.f, 0.f);
    int patho = g_patho;
    const float4* wh4 = (const float4*)g_Wh;

    for (int c = 0; c < Nn / 256; ++c) {
        int j = (c << 8) + t;
        float x = erow[j];
        float att = 0.f;
        if (x > 0.f) {
            float tt = w1 + g_Wh2[j];
            float e = (tt >= 0.f ? tt : 0.2f * tt) * x;
            att = __expf(e - g_L[k * Nn + j]);
        } else if (patho) {
            if (g_flag[k * Nn + j]) att = __expf(-g_L[k * Nn + j]);
        }
        if (write_att) arow[j] = att;

        bool nz = (att != 0.f);
        unsigned mask = __ballot_sync(0xffffffffu, nz);
        if (lane == 0) s_wcnt[w] = __popc(mask);
        __syncthreads();

        int base = 0, cnt = 0;
#pragma unroll
        for (int q = 0; q < 8; ++q) {
            int v = s_wcnt[q];
            cnt += v;
            if (q < w) base += v;
        }
        if (nz) {
            int pos = base + __popc(mask & ((1u << lane) - 1u));
            s_a[pos]  = att;
            s_jj[pos] = j;
        }
        __syncthreads();

        for (int e0 = slot; e0 < cnt; e0 += 16) {
            float a = s_a[e0];
            float4 wv = wh4[(s_jj[e0] << 4) + f4];
            acc.x += a * wv.x; acc.y += a * wv.y;
            acc.z += a * wv.z; acc.w += a * wv.w;
        }
        __syncthreads();
    }

    s_red[t] = acc;
    __syncthreads();
    if (t < 16) {
        float4 r = make_float4(0.f, 0.f, 0.f, 0.f);
#pragma unroll
        for (int sl = 0; sl < 16; ++sl) {
            float4 v = s_red[(sl << 4) + t];
            r.x += v.x; r.y += v.y; r.z += v.z; r.w += v.w;
        }
        r.x = r.x > 0.f ? r.x : expm1f(r.x);
        r.y = r.y > 0.f ? r.y : expm1f(r.y);
        r.z = r.z > 0.f ? r.z : expm1f(r.z);
        r.w = r.w > 0.f ? r.w : expm1f(r.w);
        ((float4*)out)[(size_t)i * (KH * OUTF / 4) + k * (OUTF / 4) + t] = r;
    }
}

// ============================================================
extern "C" void kernel_launch(void* const* d_in, const int* in_sizes, int n_in,
                              void* d_out, int out_size) {
    const float *h = nullptr, *edge = nullptr, *W = nullptr, *a = nullptr;
    // Identify inputs by element count (all distinct); fall back to order.
    for (int q = 0; q < n_in; ++q) {
        switch (in_sizes[q]) {
            case Nn * INF_:        h    = (const float*)d_in[q]; break; // 1,048,576
            case KH * Nn * Nn:     edge = (const float*)d_in[q]; break; // 67,108,864 -- wait, see below
            case INF_ * OUTF:      W    = (const float*)d_in[q]; break; // 16,384
            case 2 * OUTF:         a    = (const float*)d_in[q]; break; // 128
            default: break;
        }
    }
    if (!h || !edge || !W || !a) {
        if (n_in >= 4) {
            h    = (const float*)d_in[0];
            edge = (const float*)d_in[1];
            W    = (const float*)d_in[2];
            a    = (const float*)d_in[3];
        }
    }

    const long n_elu = (long)Nn * KH * OUTF;       // 1,048,576
    const long n_att = (long)KH * Nn * Nn;         // 67,108,864
    float* out = (float*)d_out;
    float* attp = out;
    int write_att = 0;
    if ((long)out_size >= n_elu + n_att) {         // tuple (elu_out, att) flattened
        attp = out + n_elu;
        write_att = 1;
    }

    k1_wh  <<<Nn / 4,            256>>>(h, W, a);
    k2_stats<<<KH * 16 * SEG,    256>>>(edge);
    k2_merge<<<KH * Nn / 256,    256>>>();
    k3_attmm<<<KH * Nn,          256>>>(edge, attp, out, write_att);
}

// round 2
// speedup vs baseline: 1.6127x; 1.6127x over previous
#include <cuda_runtime.h>

#define Nn   4096
#define INF_ 256
#define OUTF 64
#define KH   4
#define SEG  32
#define MNEG -1e30f

// ---- scratch (no allocations allowed) ----
__device__ float g_Wh[Nn * OUTF];          // 1M floats
__device__ float g_Wh1[Nn];
__device__ float g_Wh2[Nn];
__device__ float g_pm[SEG * KH * Nn];      // partial max per segment
__device__ float g_ps[SEG * KH * Nn];      // partial sum per segment
__device__ float g_L[KH * Nn];             // m + log(s) per column
__device__ unsigned char g_flag[KH * Nn];  // all-masked column flag
__device__ int g_patho;

// ============================================================
// K1: Wh = h @ W  [N,64];  Wh1 = Wh@a[:64];  Wh2 = Wh@a[64:]
// ============================================================
__global__ void __launch_bounds__(256) k1_wh(const float* __restrict__ h,
                                             const float* __restrict__ W,
                                             const float* __restrict__ a) {
    __shared__ float sh[4][INF_];
    __shared__ float s1[4], s2[4];
    int t = threadIdx.x;
    int row0 = blockIdx.x * 4;

    for (int q = t; q < 4 * INF_; q += 256)
        sh[q >> 8][q & 255] = h[(size_t)row0 * INF_ + q];
    if (t < 4) { s1[t] = 0.f; s2[t] = 0.f; }
    if (blockIdx.x == 0 && t == 0) g_patho = 0;
    __syncthreads();

    int r = t >> 6, f = t & 63;
    float acc = 0.f;
#pragma unroll 8
    for (int c = 0; c < INF_; ++c)
        acc += sh[r][c] * W[c * OUTF + f];
    g_Wh[(size_t)(row0 + r) * OUTF + f] = acc;

    float p1 = acc * a[f];
    float p2 = acc * a[OUTF + f];
#pragma unroll
    for (int o = 16; o; o >>= 1) {
        p1 += __shfl_down_sync(0xffffffffu, p1, o);
        p2 += __shfl_down_sync(0xffffffffu, p2, o);
    }
    if ((t & 31) == 0) { atomicAdd(&s1[r], p1); atomicAdd(&s2[r], p2); }
    __syncthreads();
    if (t < 4) { g_Wh1[row0 + t] = s1[t]; g_Wh2[row0 + t] = s2[t]; }
}

// ============================================================
// K2: online softmax stats over axis i, float4 across j.
// block = (k, jt of 1024 cols, i-seg of Nn/SEG); thread = 4 cols.
// ============================================================
__device__ __forceinline__ void upd(float x, float tt, float& m, float& s) {
    if (x > 0.f) {
        float e = (tt >= 0.f ? tt : 0.2f * tt) * x;
        if (e > m) { s = s * __expf(m - e) + 1.f; m = e; }
        else       { s += __expf(e - m); }
    }
}

__global__ void __launch_bounds__(256) k2_stats(const float* __restrict__ edge) {
    int b = blockIdx.x;
    int seg = b & (SEG - 1); b >>= 5;
    int jt = b & 3;
    int k  = b >> 2;
    int q = jt * 256 + threadIdx.x;                 // float4 index in row
    const float4* base = (const float4*)(edge + (size_t)k * Nn * Nn) + q;
    float4 w2 = ((const float4*)g_Wh2)[q];

    float m0 = MNEG, m1 = MNEG, m2 = MNEG, m3 = MNEG;
    float s0 = 0.f, s1 = 0.f, s2 = 0.f, s3 = 0.f;
    int i0 = seg * (Nn / SEG);
#pragma unroll 4
    for (int i = i0; i < i0 + Nn / SEG; ++i) {
        float4 x = base[(size_t)i * (Nn / 4)];
        float w1 = g_Wh1[i];
        upd(x.x, w1 + w2.x, m0, s0);
        upd(x.y, w1 + w2.y, m1, s1);
        upd(x.z, w1 + w2.z, m2, s2);
        upd(x.w, w1 + w2.w, m3, s3);
    }
    int col = seg * (KH * Nn) + k * Nn + q * 4;
    g_pm[col + 0] = m0; g_pm[col + 1] = m1; g_pm[col + 2] = m2; g_pm[col + 3] = m3;
    g_ps[col + 0] = s0; g_ps[col + 1] = s1; g_ps[col + 2] = s2; g_ps[col + 3] = s3;
}

// ============================================================
// K2b: merge segments -> L = m + log(s).
// ============================================================
__global__ void __launch_bounds__(256) k2_merge() {
    int col = blockIdx.x * 256 + threadIdx.x;
    float m = MNEG, s = 0.f;
#pragma unroll
    for (int g = 0; g < SEG; ++g) {
        float pm = g_pm[g * (KH * Nn) + col];
        float ps = g_ps[g * (KH * Nn) + col];
        if (pm > m) { s = s * __expf(m - pm) + ps; m = pm; }
        else        { s += ps * __expf(pm - m); }
    }
    if (m <= -0.9e30f) {                 // column entirely masked
        g_L[col] = logf((float)Nn);      // att = 1/N uniformly
        g_flag[col] = 1;
        atomicAdd(&g_patho, 1);
    } else {
        g_L[col] = m + logf(s);
        g_flag[col] = 0;
    }
}

// ============================================================
// K3: per (k,i): att row + sparse spmv, warp-local compaction.
// 8 warps x 512 j each; no block syncs in hot loop.
// ============================================================
__global__ void __launch_bounds__(256) k3_attmm(const float* __restrict__ edge,
                                                float* __restrict__ att_out,
                                                float* __restrict__ out,
                                                int write_att) {
    __shared__ float s_red[8][OUTF];

    int t = threadIdx.x, lane = t & 31, w = t >> 5;
    int i = blockIdx.x & (Nn - 1);
    int k = blockIdx.x >> 12;

    float w1 = g_Wh1[i];
    const float4* erow = (const float4*)(edge + (size_t)(k * Nn + i) * Nn);
    float4* arow = (float4*)(att_out + (size_t)(k * Nn + i) * Nn);
    const float4* Wh2v = (const float4*)g_Wh2;
    const float4* Lv4  = (const float4*)(g_L + k * Nn);
    const unsigned char* flag = g_flag + k * Nn;
    const float2* whp = (const float2*)g_Wh;   // Wh[j] row = 32 float2
    int patho = g_patho;

    float2 acc = make_float2(0.f, 0.f);

#pragma unroll
    for (int it = 0; it < 4; ++it) {
        int q = w * 128 + it * 32 + lane;          // float4 index
        float4 x  = erow[q];
        float4 v2 = Wh2v[q];
        float4 Lq = Lv4[q];
        int jb = q * 4;

        float4 att;
        {
            float tt, e;
            tt = w1 + v2.x;
            e = (tt >= 0.f ? tt : 0.2f * tt) * x.x;
            att.x = (x.x > 0.f) ? __expf(e - Lq.x)
                  : (patho && flag[jb + 0]) ? __expf(-Lq.x) : 0.f;
            tt = w1 + v2.y;
            e = (tt >= 0.f ? tt : 0.2f * tt) * x.y;
            att.y = (x.y > 0.f) ? __expf(e - Lq.y)
                  : (patho && flag[jb + 1]) ? __expf(-Lq.y) : 0.f;
            tt = w1 + v2.z;
            e = (tt >= 0.f ? tt : 0.2f * tt) * x.z;
            att.z = (x.z > 0.f) ? __expf(e - Lq.z)
                  : (patho && flag[jb + 2]) ? __expf(-Lq.z) : 0.f;
            tt = w1 + v2.w;
            e = (tt >= 0.f ? tt : 0.2f * tt) * x.w;
            att.w = (x.w > 0.f) ? __expf(e - Lq.w)
                  : (patho && flag[jb + 3]) ? __expf(-Lq.w) : 0.f;
        }
        if (write_att) arow[q] = att;

        int jwb = (w * 128 + it * 32) * 4;         // warp chunk base j
#pragma unroll
        for (int c = 0; c < 4; ++c) {
            float av = (c == 0) ? att.x : (c == 1) ? att.y : (c == 2) ? att.z : att.w;
            unsigned mask = __ballot_sync(0xffffffffu, av != 0.f);
            while (mask) {
                int b = __ffs(mask) - 1;
                mask &= mask - 1;
                float a = __shfl_sync(0xffffffffu, av, b);
                float2 wv = whp[(size_t)(jwb + b * 4 + c) * 32 + lane];
                acc.x += a * wv.x;
                acc.y += a * wv.y;
            }
        }
    }

    s_red[w][2 * lane]     = acc.x;
    s_red[w][2 * lane + 1] = acc.y;
    __syncthreads();
    if (t < OUTF) {
        float r = 0.f;
#pragma unroll
        for (int ww = 0; ww < 8; ++ww) r += s_red[ww][t];
        r = r > 0.f ? r : expm1f(r);
        out[(size_t)i * (KH * OUTF) + k * OUTF + t] = r;
    }
}

// ============================================================
extern "C" void kernel_launch(void* const* d_in, const int* in_sizes, int n_in,
                              void* d_out, int out_size) {
    const float *h = nullptr, *edge = nullptr, *W = nullptr, *a = nullptr;
    for (int q = 0; q < n_in; ++q) {
        switch (in_sizes[q]) {
            case Nn * INF_:    h    = (const float*)d_in[q]; break;
            case INF_ * OUTF:  W    = (const float*)d_in[q]; break;
            case 2 * OUTF:     a    = (const float*)d_in[q]; break;
            default:
                if (in_sizes[q] == KH * Nn * Nn) edge = (const float*)d_in[q];
                break;
        }
    }
    if (!h || !edge || !W || !a) {
        if (n_in >= 4) {
            h    = (const float*)d_in[0];
            edge = (const float*)d_in[1];
            W    = (const float*)d_in[2];
            a    = (const float*)d_in[3];
        }
    }

    const long n_elu = (long)Nn * KH * OUTF;
    const long n_att = (long)KH * Nn * Nn;
    float* out = (float*)d_out;
    float* attp = out;
    int write_att = 0;
    if ((long)out_size >= n_elu + n_att) {
        attp = out + n_elu;
        write_att = 1;
    }

    k1_wh   <<<Nn / 4,           256>>>(h, W, a);
    k2_stats<<<KH * 4 * SEG,     256>>>(edge);
    k2_merge<<<KH * Nn / 256,    256>>>();
    k3_attmm<<<KH * Nn,          256>>>(edge, attp, out, write_att);
}